// round 3
// baseline (speedup 1.0000x reference)
#include <cuda_runtime.h>
#include <cuda_bf16.h>
#include <math.h>

#define MAX_N 50000
#define MAX_E 800000
#define MAX_HF 256

// ---------- scratch (device globals; no allocation allowed) ----------
__device__ float g_z[(size_t)MAX_N * MAX_HF];   // per-layer projected features
__device__ float g_h[(size_t)MAX_N * MAX_HF];   // per-layer activations (next input)
__device__ float g_el[(size_t)MAX_N * 4];
__device__ float g_er[(size_t)MAX_N * 4];
__device__ int   g_cnt[MAX_N];
__device__ int   g_off[MAX_N + 1];
__device__ int   g_cur[MAX_N];
__device__ int   g_csr[MAX_E];                  // src node id per edge, grouped by dst

// ---------- CSR build ----------
__global__ void zero_cnt_kernel(int Nn) {
    int i = blockIdx.x * blockDim.x + threadIdx.x;
    if (i < Nn) g_cnt[i] = 0;
}

__global__ void count_kernel(const int* __restrict__ dst, int E) {
    int e = blockIdx.x * blockDim.x + threadIdx.x;
    if (e < E) atomicAdd(&g_cnt[dst[e]], 1);
}

// single-block scan over g_cnt -> g_off (and exclusive start in g_cur)
__global__ void scan_kernel(int Nn) {
    __shared__ int warp_sums[32];
    __shared__ int s_carry;
    int tid = threadIdx.x, lane = tid & 31, wid = tid >> 5;
    if (tid == 0) { s_carry = 0; g_off[0] = 0; }
    __syncthreads();
    for (int base = 0; base < Nn; base += (int)blockDim.x) {
        int i = base + tid;
        int v = (i < Nn) ? g_cnt[i] : 0;
        int x = v;
        #pragma unroll
        for (int o = 1; o < 32; o <<= 1) {
            int y = __shfl_up_sync(0xffffffffu, x, o);
            if (lane >= o) x += y;
        }
        if (lane == 31) warp_sums[wid] = x;
        __syncthreads();
        if (wid == 0) {
            int ws = (lane < (int)(blockDim.x >> 5)) ? warp_sums[lane] : 0;
            #pragma unroll
            for (int o = 1; o < 32; o <<= 1) {
                int y = __shfl_up_sync(0xffffffffu, ws, o);
                if (lane >= o) ws += y;
            }
            warp_sums[lane] = ws;
        }
        __syncthreads();
        int incl = x + (wid > 0 ? warp_sums[wid - 1] : 0) + s_carry;
        if (i < Nn) { g_off[i + 1] = incl; g_cur[i] = incl - v; }
        __syncthreads();
        if (tid == blockDim.x - 1) s_carry = incl;
        __syncthreads();
    }
}

__global__ void scatter_kernel(const int* __restrict__ src, const int* __restrict__ dst, int E) {
    int e = blockIdx.x * blockDim.x + threadIdx.x;
    if (e < E) {
        int p = atomicAdd(&g_cur[dst[e]], 1);
        g_csr[p] = src[e];
    }
}

// ---------- GEMM: C[M,N] = A[M,K] @ B[K,N], fp32, 128x64x16 tiles, 8x4/thread ----------
#define BM 128
#define BN 64
#define BK 16
__global__ __launch_bounds__(256) void gemm_kernel(
    const float* __restrict__ A, const float* __restrict__ B, float* __restrict__ C,
    int M, int K, int N) {
    __shared__ float sA[BK][BM + 4];
    __shared__ float sB[BK][BN + 4];
    int tid = threadIdx.x;
    int tx = tid & 15;          // 16 col-groups of 4  -> 64 cols
    int ty = tid >> 4;          // 16 row-groups of 8  -> 128 rows
    int bm0 = blockIdx.y * BM;
    int bn0 = blockIdx.x * BN;
    float acc[8][4] = {};
    for (int k0 = 0; k0 < K; k0 += BK) {
        // A tile: 128 rows x 16 k = 512 float4; 256 threads x 2
        #pragma unroll
        for (int t = 0; t < 2; ++t) {
            int flat = (tid + t * 256) * 4;
            int r = flat >> 4;          // 0..127
            int kk = flat & 15;         // multiple of 4
            float4 v = make_float4(0.f, 0.f, 0.f, 0.f);
            int grow = bm0 + r;
            if (grow < M)
                v = *reinterpret_cast<const float4*>(&A[(size_t)grow * K + k0 + kk]);
            sA[kk + 0][r] = v.x; sA[kk + 1][r] = v.y;
            sA[kk + 2][r] = v.z; sA[kk + 3][r] = v.w;
        }
        {   // B tile: 16 k x 64 cols = 256 float4; 1 per thread
            int flat = tid * 4;
            int kk = flat >> 6;         // 0..15
            int c = flat & 63;          // multiple of 4
            float4 v = make_float4(0.f, 0.f, 0.f, 0.f);
            if (bn0 + c < N)            // N always a multiple of 4
                v = *reinterpret_cast<const float4*>(&B[(size_t)(k0 + kk) * N + bn0 + c]);
            sB[kk][c + 0] = v.x; sB[kk][c + 1] = v.y;
            sB[kk][c + 2] = v.z; sB[kk][c + 3] = v.w;
        }
        __syncthreads();
        #pragma unroll
        for (int kk = 0; kk < BK; ++kk) {
            float a[8], b[4];
            #pragma unroll
            for (int i = 0; i < 8; i++) a[i] = sA[kk][ty * 8 + i];
            #pragma unroll
            for (int j = 0; j < 4; j++) b[j] = sB[kk][tx * 4 + j];
            #pragma unroll
            for (int i = 0; i < 8; i++)
                #pragma unroll
                for (int j = 0; j < 4; j++)
                    acc[i][j] += a[i] * b[j];
        }
        __syncthreads();
    }
    #pragma unroll
    for (int i = 0; i < 8; i++) {
        int r = bm0 + ty * 8 + i;
        if (r >= M) continue;
        #pragma unroll
        for (int j = 0; j < 4; j++) {
            int c = bn0 + tx * 4 + j;
            if (c < N) C[(size_t)r * N + c] = acc[i][j];
        }
    }
}

// ---------- attention scores: el/er[n,h] = sum_f z[n,h,f]*al/ar[h,f] ----------
__global__ void score_kernel(const float* __restrict__ z,
                             const float* __restrict__ al, const float* __restrict__ ar,
                             float* __restrict__ el, float* __restrict__ er,
                             int Nn, int H, int F) {
    int w = (blockIdx.x * blockDim.x + threadIdx.x) >> 5;
    int lane = threadIdx.x & 31;
    if (w >= Nn * H) return;
    int n = w / H, h = w - n * H;
    const float* zr = z + (size_t)n * H * F + (size_t)h * F;
    float a = 0.f, b = 0.f;
    for (int f = lane; f < F; f += 32) {
        float zv = zr[f];
        a += zv * al[h * F + f];
        b += zv * ar[h * F + f];
    }
    #pragma unroll
    for (int o = 16; o; o >>= 1) {
        a += __shfl_xor_sync(0xffffffffu, a, o);
        b += __shfl_xor_sync(0xffffffffu, b, o);
    }
    if (lane == 0) { el[(size_t)n * H + h] = a; er[(size_t)n * H + h] = b; }
}

// ---------- edge softmax + weighted aggregation: one warp per (dst,head) ----------
// Pass 2 unrolled x2 with independent accumulators for memory-level parallelism.
__global__ void aggregate_kernel(const float* __restrict__ z,
                                 const float* __restrict__ el, const float* __restrict__ er,
                                 const float* __restrict__ bias, float* __restrict__ out,
                                 int Nn, int H, int F, int apply_elu) {
    int w = (blockIdx.x * blockDim.x + threadIdx.x) >> 5;
    int lane = threadIdx.x & 31;
    if (w >= Nn * H) return;
    int n = w / H, h = w - n * H;
    int beg = g_off[n], end = g_off[n + 1];
    float erv = er[(size_t)n * H + h];

    // pass 1: segment max of leaky-relu scores (lane-parallel)
    float m = -1e30f;
    for (int i = beg + lane; i < end; i += 32) {
        int s = __ldg(&g_csr[i]);
        float e = __ldg(&el[s * H + h]) + erv;
        e = e > 0.f ? e : 0.2f * e;
        m = fmaxf(m, e);
    }
    #pragma unroll
    for (int o = 16; o; o >>= 1) m = fmaxf(m, __shfl_xor_sync(0xffffffffu, m, o));

    // pass 2: exp-weight accumulation, 2 edges in flight
    float acc0a = 0.f, acc1a = 0.f, swa = 0.f;
    float acc0b = 0.f, acc1b = 0.f, swb = 0.f;
    const size_t HF = (size_t)H * F;
    int i = beg;
    for (; i + 1 < end; i += 2) {
        int sA_ = __ldg(&g_csr[i]);
        int sB_ = __ldg(&g_csr[i + 1]);
        float eA = __ldg(&el[sA_ * H + h]) + erv;
        float eB = __ldg(&el[sB_ * H + h]) + erv;
        eA = eA > 0.f ? eA : 0.2f * eA;
        eB = eB > 0.f ? eB : 0.2f * eB;
        float wA = __expf(eA - m);
        float wB = __expf(eB - m);
        swa += wA; swb += wB;
        const float* zra = z + (size_t)sA_ * HF + (size_t)h * F;
        const float* zrb = z + (size_t)sB_ * HF + (size_t)h * F;
        if (lane < F) {
            acc0a += wA * __ldg(&zra[lane]);
            acc0b += wB * __ldg(&zrb[lane]);
        }
        if (lane + 32 < F) {
            acc1a += wA * __ldg(&zra[lane + 32]);
            acc1b += wB * __ldg(&zrb[lane + 32]);
        }
    }
    if (i < end) {
        int s = __ldg(&g_csr[i]);
        float e = __ldg(&el[s * H + h]) + erv;
        e = e > 0.f ? e : 0.2f * e;
        float wgt = __expf(e - m);
        swa += wgt;
        const float* zr = z + (size_t)s * HF + (size_t)h * F;
        if (lane < F)       acc0a += wgt * __ldg(&zr[lane]);
        if (lane + 32 < F)  acc1a += wgt * __ldg(&zr[lane + 32]);
    }
    float sw = swa + swb;
    float inv = (end > beg) ? 1.f / sw : 0.f;
    size_t obase = (size_t)n * HF + (size_t)h * F;
    if (lane < F) {
        float v = (acc0a + acc0b) * inv + bias[h * F + lane];
        if (apply_elu) v = v > 0.f ? v : expm1f(v);
        out[obase + lane] = v;
    }
    if (lane + 32 < F) {
        float v = (acc1a + acc1b) * inv + bias[h * F + lane + 32];
        if (apply_elu) v = v > 0.f ? v : expm1f(v);
        out[obase + lane + 32] = v;
    }
}

// ---------- launch ----------
extern "C" void kernel_launch(void* const* d_in, const int* in_sizes, int n_in,
                              void* d_out, int out_size) {
    const float* x   = (const float*)d_in[0];
    const int*   src = (const int*)d_in[1];
    const int*   dst = (const int*)d_in[2];
    const int E  = in_sizes[1];
    const int Nn = in_sizes[0] / 128;
    float* out = (float*)d_out;

    float *zp, *hp, *elp, *erp;
    cudaGetSymbolAddress((void**)&zp,  g_z);
    cudaGetSymbolAddress((void**)&hp,  g_h);
    cudaGetSymbolAddress((void**)&elp, g_el);
    cudaGetSymbolAddress((void**)&erp, g_er);

    // CSR build (dst-grouped)
    zero_cnt_kernel<<<(Nn + 255) / 256, 256>>>(Nn);
    count_kernel<<<(E + 255) / 256, 256>>>(dst, E);
    scan_kernel<<<1, 1024>>>(Nn);
    scatter_kernel<<<(E + 255) / 256, 256>>>(src, dst, E);

    struct LayerCfg { int fin, F, H; };
    const LayerCfg L[5] = {{128,64,4},{256,64,2},{128,64,2},{128,64,1},{64,4,1}};

    const float* hin = x;
    for (int l = 0; l < 5; ++l) {
        const int fin = L[l].fin, F = L[l].F, H = L[l].H, HF = H * F;
        const float* W  = (const float*)d_in[3 + 4 * l];
        const float* al = (const float*)d_in[4 + 4 * l];
        const float* ar = (const float*)d_in[5 + 4 * l];
        const float* b  = (const float*)d_in[6 + 4 * l];

        dim3 ggrid((HF + BN - 1) / BN, (Nn + BM - 1) / BM);
        gemm_kernel<<<ggrid, 256>>>(hin, W, zp, Nn, fin, HF);

        int nw = Nn * H;
        score_kernel<<<(nw * 32 + 255) / 256, 256>>>(zp, al, ar, elp, erp, Nn, H, F);

        float* o = (l == 4) ? out : hp;
        aggregate_kernel<<<(nw * 32 + 255) / 256, 256>>>(
            zp, elp, erp, b, o, Nn, H, F, l < 4 ? 1 : 0);

        hin = hp;
    }
}

// round 4
// speedup vs baseline: 1.1737x; 1.1737x over previous
#include <cuda_runtime.h>
#include <cuda_bf16.h>
#include <math.h>

#define MAX_N 50000
#define MAX_E 800000
#define MAX_HF 256

// ---------- scratch (device globals; no allocation allowed) ----------
__device__ float g_z[(size_t)MAX_N * MAX_HF];
__device__ float g_h[(size_t)MAX_N * MAX_HF];
__device__ float g_el[(size_t)MAX_N * 4];
__device__ float g_er[(size_t)MAX_N * 4];
__device__ int   g_cnt[MAX_N];
__device__ int   g_off[MAX_N + 1];
__device__ int   g_cur[MAX_N];
__device__ int   g_csr[MAX_E];

// ---------- CSR build ----------
__global__ void zero_cnt_kernel(int Nn) {
    int i = blockIdx.x * blockDim.x + threadIdx.x;
    if (i < Nn) g_cnt[i] = 0;
}

__global__ void count_kernel(const int* __restrict__ dst, int E) {
    int e = blockIdx.x * blockDim.x + threadIdx.x;
    if (e < E) atomicAdd(&g_cnt[dst[e]], 1);
}

__global__ void scan_kernel(int Nn) {
    __shared__ int warp_sums[32];
    __shared__ int s_carry;
    int tid = threadIdx.x, lane = tid & 31, wid = tid >> 5;
    if (tid == 0) { s_carry = 0; g_off[0] = 0; }
    __syncthreads();
    for (int base = 0; base < Nn; base += (int)blockDim.x) {
        int i = base + tid;
        int v = (i < Nn) ? g_cnt[i] : 0;
        int x = v;
        #pragma unroll
        for (int o = 1; o < 32; o <<= 1) {
            int y = __shfl_up_sync(0xffffffffu, x, o);
            if (lane >= o) x += y;
        }
        if (lane == 31) warp_sums[wid] = x;
        __syncthreads();
        if (wid == 0) {
            int ws = (lane < (int)(blockDim.x >> 5)) ? warp_sums[lane] : 0;
            #pragma unroll
            for (int o = 1; o < 32; o <<= 1) {
                int y = __shfl_up_sync(0xffffffffu, ws, o);
                if (lane >= o) ws += y;
            }
            warp_sums[lane] = ws;
        }
        __syncthreads();
        int incl = x + (wid > 0 ? warp_sums[wid - 1] : 0) + s_carry;
        if (i < Nn) { g_off[i + 1] = incl; g_cur[i] = incl - v; }
        __syncthreads();
        if (tid == blockDim.x - 1) s_carry = incl;
        __syncthreads();
    }
}

__global__ void scatter_kernel(const int* __restrict__ src, const int* __restrict__ dst, int E) {
    int e = blockIdx.x * blockDim.x + threadIdx.x;
    if (e < E) {
        int p = atomicAdd(&g_cur[dst[e]], 1);
        g_csr[p] = src[e];
    }
}

// ---------- tf32 tensor-core GEMM: C[M,N]=A[M,K]@B[K,N]; N%64==0, K%32==0 ----------
// 128x64 block tile, BK=32, 8 warps (4x2), 32x32 per warp, m16n8k8 tf32 mma.
__device__ __forceinline__ unsigned f2tf(float f) {
    unsigned u; asm("cvt.rna.tf32.f32 %0, %1;" : "=r"(u) : "f"(f)); return u;
}

#define TBM 128
#define TBN 64
#define TBK 32
__global__ __launch_bounds__(256) void gemm_tf32_kernel(
    const float* __restrict__ A, const float* __restrict__ B, float* __restrict__ C,
    int M, int K, int N) {
    __shared__ unsigned sA[TBM][TBK + 4];
    __shared__ unsigned sB[TBK][TBN + 8];
    int tid = threadIdx.x;
    int lane = tid & 31;
    int warp = tid >> 5;
    int wm0 = (warp >> 1) * 32;       // warp row base within tile
    int wn0 = (warp & 1) * 32;        // warp col base within tile
    int bm0 = blockIdx.y * TBM;
    int bn0 = blockIdx.x * TBN;
    int gid = lane >> 2;              // 0..7
    int tig = lane & 3;               // 0..3

    float acc[2][4][4];
    #pragma unroll
    for (int i = 0; i < 2; i++)
        #pragma unroll
        for (int j = 0; j < 4; j++)
            #pragma unroll
            for (int r = 0; r < 4; r++) acc[i][j][r] = 0.f;

    for (int k0 = 0; k0 < K; k0 += TBK) {
        // load A tile: 128 x 32 floats = 1024 float4, 4 per thread
        #pragma unroll
        for (int i = 0; i < 4; i++) {
            int t = tid + i * 256;
            int row = t >> 3;
            int kq = (t & 7) * 4;
            float4 v = make_float4(0.f, 0.f, 0.f, 0.f);
            if (bm0 + row < M)
                v = *reinterpret_cast<const float4*>(&A[(size_t)(bm0 + row) * K + k0 + kq]);
            sA[row][kq + 0] = f2tf(v.x); sA[row][kq + 1] = f2tf(v.y);
            sA[row][kq + 2] = f2tf(v.z); sA[row][kq + 3] = f2tf(v.w);
        }
        // load B tile: 32 x 64 floats = 512 float4, 2 per thread
        #pragma unroll
        for (int i = 0; i < 2; i++) {
            int t = tid + i * 256;
            int row = t >> 4;
            int cq = (t & 15) * 4;
            float4 v = *reinterpret_cast<const float4*>(&B[(size_t)(k0 + row) * N + bn0 + cq]);
            sB[row][cq + 0] = f2tf(v.x); sB[row][cq + 1] = f2tf(v.y);
            sB[row][cq + 2] = f2tf(v.z); sB[row][cq + 3] = f2tf(v.w);
        }
        __syncthreads();
        #pragma unroll
        for (int ks = 0; ks < 4; ++ks) {
            int kb = ks * 8;
            unsigned af[2][4], bf[4][2];
            #pragma unroll
            for (int mt = 0; mt < 2; ++mt) {
                int r0 = wm0 + mt * 16 + gid;
                af[mt][0] = sA[r0][kb + tig];
                af[mt][1] = sA[r0 + 8][kb + tig];
                af[mt][2] = sA[r0][kb + tig + 4];
                af[mt][3] = sA[r0 + 8][kb + tig + 4];
            }
            #pragma unroll
            for (int nt = 0; nt < 4; ++nt) {
                int c0 = wn0 + nt * 8 + gid;
                bf[nt][0] = sB[kb + tig][c0];
                bf[nt][1] = sB[kb + tig + 4][c0];
            }
            #pragma unroll
            for (int mt = 0; mt < 2; ++mt)
                #pragma unroll
                for (int nt = 0; nt < 4; ++nt) {
                    asm volatile(
                        "mma.sync.aligned.m16n8k8.row.col.f32.tf32.tf32.f32 "
                        "{%0,%1,%2,%3}, {%4,%5,%6,%7}, {%8,%9}, {%0,%1,%2,%3};"
                        : "+f"(acc[mt][nt][0]), "+f"(acc[mt][nt][1]),
                          "+f"(acc[mt][nt][2]), "+f"(acc[mt][nt][3])
                        : "r"(af[mt][0]), "r"(af[mt][1]), "r"(af[mt][2]), "r"(af[mt][3]),
                          "r"(bf[nt][0]), "r"(bf[nt][1]));
                }
        }
        __syncthreads();
    }
    // epilogue
    #pragma unroll
    for (int mt = 0; mt < 2; ++mt) {
        int r0 = bm0 + wm0 + mt * 16 + gid;
        int r1 = r0 + 8;
        #pragma unroll
        for (int nt = 0; nt < 4; ++nt) {
            int c0 = bn0 + wn0 + nt * 8 + tig * 2;
            if (r0 < M) {
                C[(size_t)r0 * N + c0]     = acc[mt][nt][0];
                C[(size_t)r0 * N + c0 + 1] = acc[mt][nt][1];
            }
            if (r1 < M) {
                C[(size_t)r1 * N + c0]     = acc[mt][nt][2];
                C[(size_t)r1 * N + c0 + 1] = acc[mt][nt][3];
            }
        }
    }
}

// ---------- SIMT GEMM fallback (layer 5: N=4) ----------
#define BM 128
#define BN 64
#define BK 16
__global__ __launch_bounds__(256) void gemm_simt_kernel(
    const float* __restrict__ A, const float* __restrict__ B, float* __restrict__ C,
    int M, int K, int N) {
    __shared__ float sA[BK][BM + 4];
    __shared__ float sB[BK][BN + 4];
    int tid = threadIdx.x;
    int tx = tid & 15, ty = tid >> 4;
    int bm0 = blockIdx.y * BM;
    int bn0 = blockIdx.x * BN;
    float acc[8][4] = {};
    for (int k0 = 0; k0 < K; k0 += BK) {
        #pragma unroll
        for (int t = 0; t < 2; ++t) {
            int flat = (tid + t * 256) * 4;
            int r = flat >> 4;
            int kk = flat & 15;
            float4 v = make_float4(0.f, 0.f, 0.f, 0.f);
            int grow = bm0 + r;
            if (grow < M)
                v = *reinterpret_cast<const float4*>(&A[(size_t)grow * K + k0 + kk]);
            sA[kk + 0][r] = v.x; sA[kk + 1][r] = v.y;
            sA[kk + 2][r] = v.z; sA[kk + 3][r] = v.w;
        }
        {
            int flat = tid * 4;
            int kk = flat >> 6;
            int c = flat & 63;
            float4 v = make_float4(0.f, 0.f, 0.f, 0.f);
            if (bn0 + c < N)
                v = *reinterpret_cast<const float4*>(&B[(size_t)(k0 + kk) * N + bn0 + c]);
            sB[kk][c + 0] = v.x; sB[kk][c + 1] = v.y;
            sB[kk][c + 2] = v.z; sB[kk][c + 3] = v.w;
        }
        __syncthreads();
        #pragma unroll
        for (int kk = 0; kk < BK; ++kk) {
            float a[8], b[4];
            #pragma unroll
            for (int i = 0; i < 8; i++) a[i] = sA[kk][ty * 8 + i];
            #pragma unroll
            for (int j = 0; j < 4; j++) b[j] = sB[kk][tx * 4 + j];
            #pragma unroll
            for (int i = 0; i < 8; i++)
                #pragma unroll
                for (int j = 0; j < 4; j++)
                    acc[i][j] += a[i] * b[j];
        }
        __syncthreads();
    }
    #pragma unroll
    for (int i = 0; i < 8; i++) {
        int r = bm0 + ty * 8 + i;
        if (r >= M) continue;
        #pragma unroll
        for (int j = 0; j < 4; j++) {
            int c = bn0 + tx * 4 + j;
            if (c < N) C[(size_t)r * N + c] = acc[i][j];
        }
    }
}

// ---------- attention scores ----------
__global__ void score_kernel(const float* __restrict__ z,
                             const float* __restrict__ al, const float* __restrict__ ar,
                             float* __restrict__ el, float* __restrict__ er,
                             int Nn, int H, int F) {
    int w = (blockIdx.x * blockDim.x + threadIdx.x) >> 5;
    int lane = threadIdx.x & 31;
    if (w >= Nn * H) return;
    int n = w / H, h = w - n * H;
    const float* zr = z + (size_t)n * H * F + (size_t)h * F;
    float a = 0.f, b = 0.f;
    for (int f = lane; f < F; f += 32) {
        float zv = zr[f];
        a += zv * al[h * F + f];
        b += zv * ar[h * F + f];
    }
    #pragma unroll
    for (int o = 16; o; o >>= 1) {
        a += __shfl_xor_sync(0xffffffffu, a, o);
        b += __shfl_xor_sync(0xffffffffu, b, o);
    }
    if (lane == 0) { el[(size_t)n * H + h] = a; er[(size_t)n * H + h] = b; }
}

// ---------- edge softmax + weighted aggregation ----------
__global__ void aggregate_kernel(const float* __restrict__ z,
                                 const float* __restrict__ el, const float* __restrict__ er,
                                 const float* __restrict__ bias, float* __restrict__ out,
                                 int Nn, int H, int F, int apply_elu) {
    int w = (blockIdx.x * blockDim.x + threadIdx.x) >> 5;
    int lane = threadIdx.x & 31;
    if (w >= Nn * H) return;
    int n = w / H, h = w - n * H;
    int beg = g_off[n], end = g_off[n + 1];
    float erv = er[(size_t)n * H + h];

    float m = -1e30f;
    for (int i = beg + lane; i < end; i += 32) {
        int s = __ldg(&g_csr[i]);
        float e = __ldg(&el[s * H + h]) + erv;
        e = e > 0.f ? e : 0.2f * e;
        m = fmaxf(m, e);
    }
    #pragma unroll
    for (int o = 16; o; o >>= 1) m = fmaxf(m, __shfl_xor_sync(0xffffffffu, m, o));

    float acc0a = 0.f, acc1a = 0.f, swa = 0.f;
    float acc0b = 0.f, acc1b = 0.f, swb = 0.f;
    const size_t HF = (size_t)H * F;
    int i = beg;
    for (; i + 1 < end; i += 2) {
        int sA_ = __ldg(&g_csr[i]);
        int sB_ = __ldg(&g_csr[i + 1]);
        float eA = __ldg(&el[sA_ * H + h]) + erv;
        float eB = __ldg(&el[sB_ * H + h]) + erv;
        eA = eA > 0.f ? eA : 0.2f * eA;
        eB = eB > 0.f ? eB : 0.2f * eB;
        float wA = __expf(eA - m);
        float wB = __expf(eB - m);
        swa += wA; swb += wB;
        const float* zra = z + (size_t)sA_ * HF + (size_t)h * F;
        const float* zrb = z + (size_t)sB_ * HF + (size_t)h * F;
        if (lane < F) {
            acc0a += wA * __ldg(&zra[lane]);
            acc0b += wB * __ldg(&zrb[lane]);
        }
        if (lane + 32 < F) {
            acc1a += wA * __ldg(&zra[lane + 32]);
            acc1b += wB * __ldg(&zrb[lane + 32]);
        }
    }
    if (i < end) {
        int s = __ldg(&g_csr[i]);
        float e = __ldg(&el[s * H + h]) + erv;
        e = e > 0.f ? e : 0.2f * e;
        float wgt = __expf(e - m);
        swa += wgt;
        const float* zr = z + (size_t)s * HF + (size_t)h * F;
        if (lane < F)       acc0a += wgt * __ldg(&zr[lane]);
        if (lane + 32 < F)  acc1a += wgt * __ldg(&zr[lane + 32]);
    }
    float sw = swa + swb;
    float inv = (end > beg) ? 1.f / sw : 0.f;
    size_t obase = (size_t)n * HF + (size_t)h * F;
    if (lane < F) {
        float v = (acc0a + acc0b) * inv + bias[h * F + lane];
        if (apply_elu) v = v > 0.f ? v : expm1f(v);
        out[obase + lane] = v;
    }
    if (lane + 32 < F) {
        float v = (acc1a + acc1b) * inv + bias[h * F + lane + 32];
        if (apply_elu) v = v > 0.f ? v : expm1f(v);
        out[obase + lane + 32] = v;
    }
}

// ---------- launch ----------
extern "C" void kernel_launch(void* const* d_in, const int* in_sizes, int n_in,
                              void* d_out, int out_size) {
    const float* x   = (const float*)d_in[0];
    const int*   src = (const int*)d_in[1];
    const int*   dst = (const int*)d_in[2];
    const int E  = in_sizes[1];
    const int Nn = in_sizes[0] / 128;
    float* out = (float*)d_out;

    float *zp, *hp, *elp, *erp;
    cudaGetSymbolAddress((void**)&zp,  g_z);
    cudaGetSymbolAddress((void**)&hp,  g_h);
    cudaGetSymbolAddress((void**)&elp, g_el);
    cudaGetSymbolAddress((void**)&erp, g_er);

    zero_cnt_kernel<<<(Nn + 255) / 256, 256>>>(Nn);
    count_kernel<<<(E + 255) / 256, 256>>>(dst, E);
    scan_kernel<<<1, 1024>>>(Nn);
    scatter_kernel<<<(E + 255) / 256, 256>>>(src, dst, E);

    struct LayerCfg { int fin, F, H; };
    const LayerCfg L[5] = {{128,64,4},{256,64,2},{128,64,2},{128,64,1},{64,4,1}};

    const float* hin = x;
    for (int l = 0; l < 5; ++l) {
        const int fin = L[l].fin, F = L[l].F, H = L[l].H, HF = H * F;
        const float* W  = (const float*)d_in[3 + 4 * l];
        const float* al = (const float*)d_in[4 + 4 * l];
        const float* ar = (const float*)d_in[5 + 4 * l];
        const float* b  = (const float*)d_in[6 + 4 * l];

        if ((HF % TBN) == 0 && (fin % TBK) == 0) {
            dim3 ggrid(HF / TBN, (Nn + TBM - 1) / TBM);
            gemm_tf32_kernel<<<ggrid, 256>>>(hin, W, zp, Nn, fin, HF);
        } else {
            dim3 ggrid((HF + BN - 1) / BN, (Nn + BM - 1) / BM);
            gemm_simt_kernel<<<ggrid, 256>>>(hin, W, zp, Nn, fin, HF);
        }

        int nw = Nn * H;
        score_kernel<<<(nw * 32 + 255) / 256, 256>>>(zp, al, ar, elp, erp, Nn, H, F);

        float* o = (l == 4) ? out : hp;
        aggregate_kernel<<<(nw * 32 + 255) / 256, 256>>>(
            zp, elp, erp, b, o, Nn, H, F, l < 4 ? 1 : 0);

        hin = hp;
    }
}